// round 6
// baseline (speedup 1.0000x reference)
#include <cuda_runtime.h>
#include <cstdint>

typedef unsigned long long ull;

#define Bn   8
#define N1   8192
#define N2   2048
#define KNN  16
#define HID  64
#define OUTC 128

// ---------------- scratch (static device globals; no allocation) ----------------
__device__ int   g_idx[Bn * N1 * KNN];     // 4 MB
__device__ float g_G2 [Bn * N2 * HID];     // 4 MB   G2 = feat2 @ W1_0[:64] + b1_0

// ---------------- packed f32x2 helpers ----------------
__device__ __forceinline__ void ffma2(ull &d, ull a, ull b) {
    asm("fma.rn.f32x2 %0, %1, %2, %0;" : "+l"(d) : "l"(a), "l"(b));
}
__device__ __forceinline__ ull pack2(float x, float y) {
    ull r; asm("mov.b64 %0, {%1, %2};" : "=l"(r) : "f"(x), "f"(y)); return r;
}
__device__ __forceinline__ void unpack2(ull v, float &x, float &y) {
    asm("mov.b64 {%0, %1}, %2;" : "=f"(x), "=f"(y) : "l"(v));
}
__device__ __forceinline__ float inff() { return __int_as_float(0x7f800000); }

// ---------------- P1: G2 = feat2 @ W1_0[0:64,:] + b1_0 ----------------
__global__ void __launch_bounds__(256) g2_kernel(const float* __restrict__ feat2,
                                                 const float* __restrict__ W1_0,
                                                 const float* __restrict__ b1_0) {
    __shared__ float sf[4][64];
    int sub = threadIdx.x >> 6;
    int ch  = threadIdx.x & 63;
    int pt  = blockIdx.x * 4 + sub;          // pt in [0, B*N2)
    sf[sub][ch] = feat2[pt * 64 + ch];
    __syncthreads();
    const float* sfr = sf[sub];
    float acc = b1_0[ch];
#pragma unroll 16
    for (int c = 0; c < 64; ++c)
        acc = fmaf(sfr[c], W1_0[c * 64 + ch], acc);
    g_G2[pt * 64 + ch] = acc;
}

// ---------------- kNN: one query per thread, two-phase select ----------------
__device__ __forceinline__ float distf(float4 p, float x, float y, float z, float s) {
    float t = p.x * x;
    t = fmaf(p.y, y, t);
    t = fmaf(p.z, z, t);
    return fmaf(-2.0f, t, s + p.w);
}

__global__ void __launch_bounds__(128) knn_kernel(const float* __restrict__ xyz1,
                                                  const float* __restrict__ xyz2) {
    __shared__ float4 s2[N2];                 // 32 KB: (x,y,z,|p|^2)
    int b = blockIdx.y;
    const float* x2 = xyz2 + (size_t)b * N2 * 3;
    for (int i = threadIdx.x; i < N2; i += 128) {
        float px = x2[i * 3 + 0], py = x2[i * 3 + 1], pz = x2[i * 3 + 2];
        s2[i] = make_float4(px, py, pz, fmaf(px, px, fmaf(py, py, pz * pz)));
    }
    __syncthreads();

    int n = blockIdx.x * 128 + threadIdx.x;   // query within batch
    int q = b * N1 + n;
    float x1x = xyz1[q * 3 + 0], x1y = xyz1[q * 3 + 1], x1z = xyz1[q * 3 + 2];
    float x1sq = fmaf(x1x, x1x, fmaf(x1y, x1y, x1z * x1z));

    // phase 1: exact 16th-smallest distance via branch-free sorted chain
    float best[KNN];
#pragma unroll
    for (int i = 0; i < KNN; ++i) best[i] = inff();

    for (int c = 0; c < N2; ++c) {
        float4 p = s2[c];
        float d = distf(p, x1x, x1y, x1z, x1sq);
        bool act = d < best[KNN - 1];
        if (__ballot_sync(0xffffffffu, act)) {
            float v = act ? d : inff();       // INF insert = no-op, keeps warp uniform
#pragma unroll
            for (int i = 0; i < KNN; ++i) {
                float t = fminf(v, best[i]);
                v = fmaxf(v, best[i]);
                best[i] = t;
            }
        }
    }
    float tau = best[KNN - 1];

    // phase 2: collect indices with d <= tau (identical arithmetic), cap at 16
    int cnt = 0, lastc = 0;
    int* myout = g_idx + (size_t)q * KNN;
    for (int c = 0; c < N2; ++c) {
        float4 p = s2[c];
        float d = distf(p, x1x, x1y, x1z, x1sq);
        if (d <= tau && cnt < KNN) {
            myout[cnt++] = c;
            lastc = c;
        }
    }
    for (; cnt < KNN; ++cnt) myout[cnt] = lastc;   // safety fill (ties/ulp)
}

// ---------------- MLP kernel: warp per query ----------------
#define BWARPS   6
#define BTHREADS 192
#define HSTRIDE  18                        // 16 k-slots + pad, 8B-aligned rows
#define SW11_F   4096                      // 64*64
#define SW2_F    16384                     // 128*128
#define SH_F     (BWARPS * 64 * HSTRIDE)   // per-warp H1^T buffers
#define SMEM_F   (SW11_F + SW2_F + SH_F + BWARPS * 16)
#define SMEM_B_BYTES (SMEM_F * 4)

__global__ void __launch_bounds__(BTHREADS, 2)
mlp_kernel(const float* __restrict__ xyz1, const float* __restrict__ feat1,
           const float* __restrict__ xyz2,
           const float* __restrict__ W1_0, const float* __restrict__ W1_1,
           const float* __restrict__ b1_1, const float* __restrict__ W2_0,
           const float* __restrict__ b2_0, float* __restrict__ out) {
    extern __shared__ float sm[];
    float* sW11 = sm;
    float* sW2  = sm + SW11_F;
    float* sH   = sm + SW11_F + SW2_F;
    int*   sIdx = (int*)(sm + SW11_F + SW2_F + SH_F);

    int tid = threadIdx.x, w = tid >> 5, lane = tid & 31;

    for (int i = tid; i < SW11_F; i += BTHREADS) sW11[i] = W1_1[i];
    for (int i = tid; i < SW2_F;  i += BTHREADS) sW2[i]  = W2_0[i];

    // per-lane constant weights (xyz rows of W1_0, biases)
    float wx0 = W1_0[64 * 64 + 2 * lane], wx1 = W1_0[64 * 64 + 2 * lane + 1];
    float wy0 = W1_0[65 * 64 + 2 * lane], wy1 = W1_0[65 * 64 + 2 * lane + 1];
    float wz0 = W1_0[66 * 64 + 2 * lane], wz1 = W1_0[66 * 64 + 2 * lane + 1];
    float bb0 = b1_1[2 * lane], bb1 = b1_1[2 * lane + 1];
    float4 b2v = *(const float4*)&b2_0[4 * lane];
    __syncthreads();

    float* myH   = sH + w * (64 * HSTRIDE);
    int*   myIdx = sIdx + w * 16;
    int nwarps = gridDim.x * BWARPS;

    for (int q = blockIdx.x * BWARPS + w; q < Bn * N1; q += nwarps) {
        int b = q >> 13;
        if (lane < 16) myIdx[lane] = g_idx[(size_t)q * KNN + lane];
        float x1x = xyz1[q * 3 + 0], x1y = xyz1[q * 3 + 1], x1z = xyz1[q * 3 + 2];
        __syncwarp();

        // ---- layer 1: h = relu(G2[idx] + diff @ W1_0[64:67]) ----
#pragma unroll
        for (int k = 0; k < KNN; ++k) {
            int ik = myIdx[k];
            const float* gr = g_G2 + ((size_t)(b << 11) + ik) * 64;
            float2 g = *(const float2*)&gr[2 * lane];
            const float* p2 = xyz2 + ((size_t)(b << 11) + ik) * 3;
            float dx = p2[0] - x1x, dy = p2[1] - x1y, dz = p2[2] - x1z;
            float h0 = fmaf(dz, wz0, fmaf(dy, wy0, fmaf(dx, wx0, g.x)));
            float h1 = fmaf(dz, wz1, fmaf(dy, wy1, fmaf(dx, wx1, g.y)));
            myH[(2 * lane)     * HSTRIDE + k] = fmaxf(h0, 0.f);
            myH[(2 * lane + 1) * HSTRIDE + k] = fmaxf(h1, 0.f);
        }
        __syncwarp();

        // ---- layer 2 (FFMA2, k-paired accumulators) ----
        ull acc0[8], acc1[8];
#pragma unroll
        for (int kk = 0; kk < 8; ++kk) { acc0[kk] = 0ull; acc1[kk] = 0ull; }
#pragma unroll 4
        for (int c = 0; c < 64; ++c) {
            float2 wv = *(const float2*)&sW11[c * 64 + 2 * lane];
            ull w00 = pack2(wv.x, wv.x);
            ull w11 = pack2(wv.y, wv.y);
            const float* hr = myH + c * HSTRIDE;
#pragma unroll
            for (int kk = 0; kk < 8; ++kk) {
                ull in2 = *(const ull*)&hr[2 * kk];
                ffma2(acc0[kk], in2, w00);
                ffma2(acc1[kk], in2, w11);
            }
        }

        // ---- maxpool over k, bias, relu ----
        float m0 = -inff(), m1 = -inff();
#pragma unroll
        for (int kk = 0; kk < 8; ++kk) {
            float a, bh;
            unpack2(acc0[kk], a, bh); m0 = fmaxf(m0, fmaxf(a, bh));
            unpack2(acc1[kk], a, bh); m1 = fmaxf(m1, fmaxf(a, bh));
        }
        float p0 = fmaxf(m0 + bb0, 0.f);
        float p1 = fmaxf(m1 + bb1, 0.f);

        // ---- stage [pooled(64), feat1(64)] ----
        *(float2*)&myH[2 * lane] = make_float2(p0, p1);
        float2 f1v = *(const float2*)&feat1[(size_t)q * 64 + 2 * lane];
        *(float2*)&myH[64 + 2 * lane] = f1v;
        __syncwarp();

        // ---- final layer: relu(in @ W2_0 + b2_0), lane owns 4 out channels ----
        ull o0 = pack2(b2v.x, b2v.y);
        ull o1 = pack2(b2v.z, b2v.w);
#pragma unroll 4
        for (int c = 0; c < 128; ++c) {
            float in = myH[c];
            ull in2 = pack2(in, in);
            ulonglong2 wv = *(const ulonglong2*)&sW2[c * 128 + 4 * lane];
            ffma2(o0, in2, wv.x);
            ffma2(o1, in2, wv.y);
        }
        float r0, r1, r2, r3;
        unpack2(o0, r0, r1);
        unpack2(o1, r2, r3);
        float4 res = make_float4(fmaxf(r0, 0.f), fmaxf(r1, 0.f),
                                 fmaxf(r2, 0.f), fmaxf(r3, 0.f));
        *(float4*)&out[(size_t)q * OUTC + 4 * lane] = res;
        __syncwarp();
    }
}

// ---------------- launch ----------------
extern "C" void kernel_launch(void* const* d_in, const int* in_sizes, int n_in,
                              void* d_out, int out_size) {
    const float* xyz1  = (const float*)d_in[0];
    const float* feat1 = (const float*)d_in[1];
    const float* xyz2  = (const float*)d_in[2];
    const float* feat2 = (const float*)d_in[3];
    const float* W1_0  = (const float*)d_in[4];
    const float* b1_0  = (const float*)d_in[5];
    const float* W1_1  = (const float*)d_in[6];
    const float* b1_1  = (const float*)d_in[7];
    const float* W2_0  = (const float*)d_in[8];
    const float* b2_0  = (const float*)d_in[9];
    float* out = (float*)d_out;

    cudaFuncSetAttribute(mlp_kernel, cudaFuncAttributeMaxDynamicSharedMemorySize,
                         SMEM_B_BYTES);

    g2_kernel<<<(Bn * N2) / 4, 256>>>(feat2, W1_0, b1_0);
    knn_kernel<<<dim3(N1 / 128, Bn), 128>>>(xyz1, xyz2);
    mlp_kernel<<<296, BTHREADS, SMEM_B_BYTES>>>(xyz1, feat1, xyz2, W1_0, W1_1,
                                                b1_1, W2_0, b2_0, out);
}